// round 15
// baseline (speedup 1.0000x reference)
#include <cuda_runtime.h>
#include <cuda_bf16.h>

#define EPS 1e-12f

__device__ __forceinline__ float sel4(float4 q, int r) {
    float v = q.x;
    if (r == 1) v = q.y;
    if (r == 2) v = q.z;
    if (r == 3) v = q.w;
    return v;
}

// Adjacent pair (vrow[i], vrow[i+1]) via ONE aligned LDG.128 + predicated
// scalar fixup for i%4==3 (25%). 1.25 wavefronts/lane, traffic-neutral.
__device__ __forceinline__ float2 pair_ld(const float* __restrict__ vrow, int i) {
    int base = i & ~3;
    int r    = i & 3;
    float4 q = __ldg(reinterpret_cast<const float4*>(vrow + base));
    float v0 = sel4(q, r);
    float v1 = sel4(q, min(r + 1, 3));
    if (r == 3) v1 = __ldg(vrow + i + 1);
    return make_float2(v0, v1);
}

// Fully branchless single-eval body (R12/R14 structure): only predicated
// loads and selects — no real branches, so two inlined copies form one
// straight-line region and ptxas can front-batch BOTH evals' gathers.
__device__ __forceinline__ float eval_branchless(float x_t, float x_c, int a,
                                                 const float* __restrict__ vals,
                                                 const float* __restrict__ t_tbl,
                                                 const float* __restrict__ c_tbl,
                                                 const int*   __restrict__ dims)
{
    int2 d = __ldg(reinterpret_cast<const int2*>(dims) + a);
    int td = d.x, cd = d.y;
    bool valid = (td > 0) && (cd > 0);

    // table gathers, two-level predication (traffic-optimal, R12-proven)
    const float4* tt4 = reinterpret_cast<const float4*>(t_tbl) + 2 * a;
    const float4* ct4 = reinterpret_cast<const float4*>(c_tbl) + 2 * a;
    const float INF = __int_as_float(0x7f800000);
    float4 tA, tB, cA, cB;
    if (td > 1) {
        tA = __ldg(tt4);
        if (td >= 5) tB = __ldg(tt4 + 1);
        else         tB = make_float4(INF, INF, INF, INF);
    } else {
        tA = make_float4(0.f, 0.f, 0.f, 0.f);
        tB = tA;
    }
    if (cd > 1) {
        cA = __ldg(ct4);
        if (cd >= 5) cB = __ldg(ct4 + 1);
        else         cB = make_float4(INF, INF, INF, INF);
    } else {
        cA = make_float4(0.f, 0.f, 0.f, 0.f);
        cB = cA;
    }

    float tv[8] = {tA.x, tA.y, tA.z, tA.w, tB.x, tB.y, tB.z, tB.w};
    float cv[8] = {cA.x, cA.y, cA.z, cA.w, cB.x, cB.y, cB.z, cB.w};

    // searchsorted side='right' = count of (tbl <= x); INF contributes 0,
    // zeroed table counts 8 -> clamped to 0 below
    int ss_t = 0, ss_c = 0;
    #pragma unroll
    for (int j = 0; j < 8; ++j) {
        ss_t += (tv[j] <= x_t) ? 1 : 0;
        ss_c += (cv[j] <= x_c) ? 1 : 0;
    }

    int max_t = max(td - 1, 0);
    int max_c = max(cd - 1, 0);
    // clamp(min=1) then clamp(max=dim-1), matching the reference order
    int t_hi = min(max(ss_t, 1), max_t);
    int c_hi = min(max(ss_c, 1), max_c);
    int t_lo = max(t_hi - 1, 0);
    int c_lo = max(c_hi - 1, 0);

    // register-resident breakpoint selection (SEL chains)
    float t0 = tv[0], t1 = tv[0], c0 = cv[0], c1 = cv[0];
    #pragma unroll
    for (int j = 1; j < 8; ++j) {
        if (t_lo == j) t0 = tv[j];
        if (t_hi == j) t1 = tv[j];
        if (c_lo == j) c0 = cv[j];
        if (c_hi == j) c1 = cv[j];
    }

    // Degeneracy: steps >= 0.01 -> dim>1 never "deg"; dim<=1 lanes have
    // t0==t1 exactly -> f = 0 exactly. Unified lerp == reference selects
    // (R12/R13/R14-verified, rel_err 7e-8).
    float ti = t1 - t0;
    float ci = c1 - c0;
    float ti_s = (fabsf(ti) < EPS) ? EPS : ti;
    float ci_s = (fabsf(ci) < EPS) ? EPS : ci;

    float xt = fminf(fmaxf(x_t, t0), t1);
    float xc = fminf(fmaxf(x_c, c0), c1);

    float ft = fminf(fmaxf(__fdividef(xt - t0, ti_s), 0.0f), 1.0f);
    float fc = fminf(fmaxf(__fdividef(xc - c0, ci_s), 0.0f), 1.0f);

    // unified branchless corner addressing
    bool is2d = (td > 1) && (cd > 1);
    bool is1t = (td > 1) && (cd <= 1);
    int  i00  = t_lo * (is2d ? cd : 1) + c_lo;

    float fA = is1t ? ft : fc;
    float fB = is1t ? 0.0f : ft;

    const float* vrow = vals + (size_t)a * 64;

    // value pairs, predicated on valid (invalid lanes load nothing)
    float2 p0 = make_float2(0.f, 0.f);
    if (valid) p0 = pair_ld(vrow, i00);
    float2 p1 = p0;
    if (is2d) p1 = pair_ld(vrow, i00 + cd);

    float rowA = p0.x + (p0.y - p0.x) * fA;
    float rowB = p1.x + (p1.y - p1.x) * fA;
    float res  = rowA + (rowB - rowA) * fB;

    return valid ? res : 0.0f;
}

__global__ __launch_bounds__(256)
void timing_prop_kernel(const float* __restrict__ x_t_arr,
                        const float* __restrict__ x_c_arr,
                        const int*   __restrict__ arc_idxs,
                        const float* __restrict__ vals,
                        const float* __restrict__ t_tbl,
                        const float* __restrict__ c_tbl,
                        const int*   __restrict__ dims,
                        float*       __restrict__ out,
                        int B)
{
    int i  = blockIdx.x * blockDim.x + threadIdx.x;
    int b0 = 2 * i;
    if (b0 >= B) return;

    if (b0 + 1 < B) {
        // vectorized streamed I/O (zero reuse -> evict-first)
        float2 xt2 = __ldcs(reinterpret_cast<const float2*>(x_t_arr) + i);
        float2 xc2 = __ldcs(reinterpret_cast<const float2*>(x_c_arr) + i);
        int2   a2  = __ldcs(reinterpret_cast<const int2*>(arc_idxs) + i);

        // two branchless chains in one straight-line region -> ptxas
        // front-batches both evals' gathers (2x per-warp MLP)
        float r0 = eval_branchless(xt2.x, xc2.x, a2.x, vals, t_tbl, c_tbl, dims);
        float r1 = eval_branchless(xt2.y, xc2.y, a2.y, vals, t_tbl, c_tbl, dims);

        __stcs(reinterpret_cast<float2*>(out) + i, make_float2(r0, r1));
    } else {
        float x_t = __ldcs(x_t_arr + b0);
        float x_c = __ldcs(x_c_arr + b0);
        int   a   = __ldcs(arc_idxs + b0);
        float r   = eval_branchless(x_t, x_c, a, vals, t_tbl, c_tbl, dims);
        __stcs(out + b0, r);
    }
}

extern "C" void kernel_launch(void* const* d_in, const int* in_sizes, int n_in,
                              void* d_out, int out_size)
{
    const float* input_trans = (const float*)d_in[0];
    const float* output_caps = (const float*)d_in[1];
    const int*   arc_idxs    = (const int*)d_in[2];
    const float* vals        = (const float*)d_in[3];
    const float* t_tbl       = (const float*)d_in[4];
    const float* c_tbl       = (const float*)d_in[5];
    const int*   dims        = (const int*)d_in[6];
    float*       out         = (float*)d_out;

    int B = in_sizes[0];
    int threads = 256;
    int evals_per_block = threads * 2;
    int blocks = (B + evals_per_block - 1) / evals_per_block;
    timing_prop_kernel<<<blocks, threads>>>(input_trans, output_caps, arc_idxs,
                                            vals, t_tbl, c_tbl, dims, out, B);
}

// round 16
// speedup vs baseline: 1.1096x; 1.1096x over previous
#include <cuda_runtime.h>
#include <cuda_bf16.h>

#define EPS 1e-12f

__device__ __forceinline__ float sel4(float4 q, int r) {
    float v = q.x;
    if (r == 1) v = q.y;
    if (r == 2) v = q.z;
    if (r == 3) v = q.w;
    return v;
}

// Adjacent pair (vrow[i], vrow[i+1]) via ONE aligned LDG.128 + predicated
// scalar fixup for i%4==3 (25%). 1.25 wavefronts/lane, traffic-neutral.
__device__ __forceinline__ float2 pair_ld(const float* __restrict__ vrow, int i) {
    int base = i & ~3;
    int r    = i & 3;
    float4 q = __ldg(reinterpret_cast<const float4*>(vrow + base));
    float v0 = sel4(q, r);
    float v1 = sel4(q, min(r + 1, 3));
    if (r == 3) v1 = __ldg(vrow + i + 1);
    return make_float2(v0, v1);
}

__global__ __launch_bounds__(256, 8)   // force regs<=32 so 8 CTAs/SM resident
void timing_prop_kernel(const float* __restrict__ x_t_arr,
                        const float* __restrict__ x_c_arr,
                        const int*   __restrict__ arc_idxs,
                        const float* __restrict__ vals,
                        const float* __restrict__ t_tbl,
                        const float* __restrict__ c_tbl,
                        const int*   __restrict__ dims,
                        float*       __restrict__ out,
                        int B)
{
    const int stride = gridDim.x * blockDim.x;

    // persistent grid-stride: exactly one wave of CTAs, no wave transitions;
    // successive iterations pipeline naturally (independent work, streamed
    // addresses are induction-variable offsets ptxas can hoist early)
    for (int b = blockIdx.x * blockDim.x + threadIdx.x; b < B; b += stride) {

        // streamed, zero-reuse -> evict-first (keep L2 for tables/values)
        float x_t = __ldcs(x_t_arr + b);
        float x_c = __ldcs(x_c_arr + b);
        int   a   = __ldcs(arc_idxs + b);

        // dims gather (hot, cached)
        int2 d = __ldg(reinterpret_cast<const int2*>(dims) + a);
        int td = d.x, cd = d.y;

        if (td <= 0 || cd <= 0) { __stcs(out + b, 0.0f); continue; }

        // ---- table gathers, two-level predication (R12/R14-proven) ----
        // dim<=1 : table irrelevant -> zeros (hi=lo=0, t0==t1 -> f=0 exactly)
        // 2..4   : second float4 provably can't change clamped result -> +INF
        // >=5    : both halves
        const float4* tt4 = reinterpret_cast<const float4*>(t_tbl) + 2 * a;
        const float4* ct4 = reinterpret_cast<const float4*>(c_tbl) + 2 * a;
        const float INF = __int_as_float(0x7f800000);
        float4 tA, tB, cA, cB;
        if (td > 1) {
            tA = __ldg(tt4);
            if (td >= 5) tB = __ldg(tt4 + 1);
            else         tB = make_float4(INF, INF, INF, INF);
        } else {
            tA = make_float4(0.f, 0.f, 0.f, 0.f);
            tB = tA;
        }
        if (cd > 1) {
            cA = __ldg(ct4);
            if (cd >= 5) cB = __ldg(ct4 + 1);
            else         cB = make_float4(INF, INF, INF, INF);
        } else {
            cA = make_float4(0.f, 0.f, 0.f, 0.f);
            cB = cA;
        }

        float tv[8] = {tA.x, tA.y, tA.z, tA.w, tB.x, tB.y, tB.z, tB.w};
        float cv[8] = {cA.x, cA.y, cA.z, cA.w, cB.x, cB.y, cB.z, cB.w};

        // searchsorted side='right' = count of (tbl <= x); INF contributes 0,
        // zeroed table counts 8 -> clamped to 0 below
        int ss_t = 0, ss_c = 0;
        #pragma unroll
        for (int j = 0; j < 8; ++j) {
            ss_t += (tv[j] <= x_t) ? 1 : 0;
            ss_c += (cv[j] <= x_c) ? 1 : 0;
        }

        int max_t = max(td - 1, 0);
        int max_c = max(cd - 1, 0);
        // clamp(min=1) then clamp(max=dim-1), matching the reference order
        int t_hi = min(max(ss_t, 1), max_t);
        int c_hi = min(max(ss_c, 1), max_c);
        int t_lo = max(t_hi - 1, 0);
        int c_lo = max(c_hi - 1, 0);

        // register-resident breakpoint selection (SEL chains)
        float t0 = tv[0], t1 = tv[0], c0 = cv[0], c1 = cv[0];
        #pragma unroll
        for (int j = 1; j < 8; ++j) {
            if (t_lo == j) t0 = tv[j];
            if (t_hi == j) t1 = tv[j];
            if (c_lo == j) c0 = cv[j];
            if (c_hi == j) c1 = cv[j];
        }

        // Degeneracy: steps >= 0.01 -> dim>1 lanes never "deg"; dim<=1 lanes
        // have t0==t1 exactly -> f = 0 exactly. Unified lerp == reference
        // selects in every reachable case (R12-R14 verified, rel_err 7e-8).
        float ti = t1 - t0;
        float ci = c1 - c0;
        float ti_s = (fabsf(ti) < EPS) ? EPS : ti;
        float ci_s = (fabsf(ci) < EPS) ? EPS : ci;

        float xt = fminf(fmaxf(x_t, t0), t1);
        float xc = fminf(fmaxf(x_c, c0), c1);

        float ft = fminf(fmaxf(__fdividef(xt - t0, ti_s), 0.0f), 1.0f);
        float fc = fminf(fmaxf(__fdividef(xc - c0, ci_s), 0.0f), 1.0f);

        // ---- unified branchless corner addressing ----
        bool is2d = (td > 1) && (cd > 1);
        bool is1t = (td > 1) && (cd <= 1);
        int  i00  = t_lo * (is2d ? cd : 1) + c_lo;

        float fA = is1t ? ft : fc;
        float fB = is1t ? 0.0f : ft;

        const float* vrow = vals + (size_t)a * 64;

        // value pairs: always adjacent (hi == lo+1 whenever dim>1)
        float2 p0 = pair_ld(vrow, i00);
        float2 p1 = p0;
        if (is2d) p1 = pair_ld(vrow, i00 + cd);   // predicated: only 2D lanes

        float rowA = p0.x + (p0.y - p0.x) * fA;
        float rowB = p1.x + (p1.y - p1.x) * fA;
        float res  = rowA + (rowB - rowA) * fB;

        __stcs(out + b, res);
    }
}

extern "C" void kernel_launch(void* const* d_in, const int* in_sizes, int n_in,
                              void* d_out, int out_size)
{
    const float* input_trans = (const float*)d_in[0];
    const float* output_caps = (const float*)d_in[1];
    const int*   arc_idxs    = (const int*)d_in[2];
    const float* vals        = (const float*)d_in[3];
    const float* t_tbl       = (const float*)d_in[4];
    const float* c_tbl       = (const float*)d_in[5];
    const int*   dims        = (const int*)d_in[6];
    float*       out         = (float*)d_out;

    int B = in_sizes[0];
    int threads = 256;
    // exactly one wave: 148 SMs x 8 resident CTAs (regs capped at 32)
    int blocks = 148 * 8;
    int max_blocks = (B + threads - 1) / threads;
    if (blocks > max_blocks) blocks = max_blocks;
    timing_prop_kernel<<<blocks, threads>>>(input_trans, output_caps, arc_idxs,
                                            vals, t_tbl, c_tbl, dims, out, B);
}

// round 17
// speedup vs baseline: 1.1159x; 1.0057x over previous
#include <cuda_runtime.h>
#include <cuda_bf16.h>

#define EPS 1e-12f

__device__ __forceinline__ float sel4(float4 q, int r) {
    float v = q.x;
    if (r == 1) v = q.y;
    if (r == 2) v = q.z;
    if (r == 3) v = q.w;
    return v;
}

// Adjacent pair (vrow[i], vrow[i+1]) via ONE aligned LDG.128 + predicated
// scalar fixup for i%4==3 (25%). 1.25 wavefronts/lane, traffic-neutral.
__device__ __forceinline__ float2 pair_ld(const float* __restrict__ vrow, int i) {
    int base = i & ~3;
    int r    = i & 3;
    float4 q = __ldg(reinterpret_cast<const float4*>(vrow + base));
    float v0 = sel4(q, r);
    float v1 = sel4(q, min(r + 1, 3));
    if (r == 3) v1 = __ldg(vrow + i + 1);
    return make_float2(v0, v1);
}

__global__ __launch_bounds__(256, 8)   // force regs<=32 so 8 CTAs/SM resident
void timing_prop_kernel(const float* __restrict__ x_t_arr,
                        const float* __restrict__ x_c_arr,
                        const int*   __restrict__ arc_idxs,
                        const float* __restrict__ vals,
                        const float* __restrict__ t_tbl,
                        const float* __restrict__ c_tbl,
                        const int*   __restrict__ dims,
                        float*       __restrict__ out,
                        int B)
{
    const int stride = gridDim.x * blockDim.x;
    const float INF = __int_as_float(0x7f800000);

    // persistent grid-stride: exactly one wave of CTAs on all 152 SMs
    for (int b = blockIdx.x * blockDim.x + threadIdx.x; b < B; b += stride) {

        // streamed, zero-reuse -> evict-first (keep L2 for tables/values)
        float x_t = __ldcs(x_t_arr + b);
        float x_c = __ldcs(x_c_arr + b);
        int   a   = __ldcs(arc_idxs + b);

        // dims gather (hot, cached)
        int2 d = __ldg(reinterpret_cast<const int2*>(dims) + a);
        int td = d.x, cd = d.y;

        if (td <= 0 || cd <= 0) { __stcs(out + b, 0.0f); continue; }

        // ---- table gathers, two-level predication (R12/R14-proven) ----
        // dim<=1 : table irrelevant -> zeros (hi=lo=0, t0==t1 -> f=0 exactly)
        // 2..4   : second float4 provably can't change clamped result -> +INF
        // >=5    : both halves
        const float4* tt4 = reinterpret_cast<const float4*>(t_tbl) + 2 * a;
        const float4* ct4 = reinterpret_cast<const float4*>(c_tbl) + 2 * a;
        float4 tA, tB, cA, cB;
        if (td > 1) {
            tA = __ldg(tt4);
            if (td >= 5) tB = __ldg(tt4 + 1);
            else         tB = make_float4(INF, INF, INF, INF);
        } else {
            tA = make_float4(0.f, 0.f, 0.f, 0.f);
            tB = tA;
        }
        if (cd > 1) {
            cA = __ldg(ct4);
            if (cd >= 5) cB = __ldg(ct4 + 1);
            else         cB = make_float4(INF, INF, INF, INF);
        } else {
            cA = make_float4(0.f, 0.f, 0.f, 0.f);
            cB = cA;
        }

        float tv[8] = {tA.x, tA.y, tA.z, tA.w, tB.x, tB.y, tB.z, tB.w};
        float cv[8] = {cA.x, cA.y, cA.z, cA.w, cB.x, cB.y, cB.z, cB.w};

        // searchsorted side='right' = count of (tbl <= x); INF contributes 0,
        // zeroed table counts 8 -> clamped to 0 below
        int ss_t = 0, ss_c = 0;
        #pragma unroll
        for (int j = 0; j < 8; ++j) {
            ss_t += (tv[j] <= x_t) ? 1 : 0;
            ss_c += (cv[j] <= x_c) ? 1 : 0;
        }

        int max_t = max(td - 1, 0);
        int max_c = max(cd - 1, 0);
        // clamp(min=1) then clamp(max=dim-1), matching the reference order
        int t_hi = min(max(ss_t, 1), max_t);
        int c_hi = min(max(ss_c, 1), max_c);
        int t_lo = max(t_hi - 1, 0);
        int c_lo = max(c_hi - 1, 0);

        // register-resident breakpoint selection (SEL chains)
        float t0 = tv[0], t1 = tv[0], c0 = cv[0], c1 = cv[0];
        #pragma unroll
        for (int j = 1; j < 8; ++j) {
            if (t_lo == j) t0 = tv[j];
            if (t_hi == j) t1 = tv[j];
            if (c_lo == j) c0 = cv[j];
            if (c_hi == j) c1 = cv[j];
        }

        // Degeneracy: steps >= 0.01 -> dim>1 lanes never "deg"; dim<=1 lanes
        // have t0==t1 exactly -> f = 0 exactly. Unified lerp == reference
        // selects in every reachable case (R12-R16 verified, rel_err 7e-8).
        float ti = t1 - t0;
        float ci = c1 - c0;
        float ti_s = (fabsf(ti) < EPS) ? EPS : ti;
        float ci_s = (fabsf(ci) < EPS) ? EPS : ci;

        float xt = fminf(fmaxf(x_t, t0), t1);
        float xc = fminf(fmaxf(x_c, c0), c1);

        float ft = fminf(fmaxf(__fdividef(xt - t0, ti_s), 0.0f), 1.0f);
        float fc = fminf(fmaxf(__fdividef(xc - c0, ci_s), 0.0f), 1.0f);

        // ---- unified branchless corner addressing ----
        bool is2d = (td > 1) && (cd > 1);
        bool is1t = (td > 1) && (cd <= 1);
        int  i00  = t_lo * (is2d ? cd : 1) + c_lo;

        float fA = is1t ? ft : fc;
        float fB = is1t ? 0.0f : ft;

        const float* vrow = vals + (size_t)a * 64;

        // value pairs: always adjacent (hi == lo+1 whenever dim>1)
        float2 p0 = pair_ld(vrow, i00);
        float2 p1 = p0;
        if (is2d) p1 = pair_ld(vrow, i00 + cd);   // predicated: only 2D lanes

        float rowA = p0.x + (p0.y - p0.x) * fA;
        float rowB = p1.x + (p1.y - p1.x) * fA;
        float res  = rowA + (rowB - rowA) * fB;

        __stcs(out + b, res);
    }
}

extern "C" void kernel_launch(void* const* d_in, const int* in_sizes, int n_in,
                              void* d_out, int out_size)
{
    const float* input_trans = (const float*)d_in[0];
    const float* output_caps = (const float*)d_in[1];
    const int*   arc_idxs    = (const int*)d_in[2];
    const float* vals        = (const float*)d_in[3];
    const float* t_tbl       = (const float*)d_in[4];
    const float* c_tbl       = (const float*)d_in[5];
    const int*   dims        = (const int*)d_in[6];
    float*       out         = (float*)d_out;

    int B = in_sizes[0];
    int threads = 256;
    // exactly one wave on GB300: 152 SMs x 8 resident CTAs (regs capped at 32)
    int blocks = 152 * 8;
    int max_blocks = (B + threads - 1) / threads;
    if (blocks > max_blocks) blocks = max_blocks;
    timing_prop_kernel<<<blocks, threads>>>(input_trans, output_caps, arc_idxs,
                                            vals, t_tbl, c_tbl, dims, out, B);
}